// round 4
// baseline (speedup 1.0000x reference)
#include <cuda_runtime.h>

// Problem constants (fixed by the reference): B=8, C=64, H=W=256.
#define Bn   8
#define Cn   64
#define Hn   256
#define Wn   256
#define HWn  (Hn * Wn)          // 65536
#define NPIX (Bn * HWn)         // 524288
#define FULLM 0xFFFFFFFFu
#define WPB  4                  // warps per block
#define TPB  (WPB * 32)

// Warp-cooperative layout:
//   warp  = 32 consecutive pixels (one hw row segment), ALL 64 channels.
//   lane  = one pixel for weight computation + coalesced stores,
//           one channel for cooperative gathers.
__global__ __launch_bounds__(TPB)
void warp_bilinear_kernel(const float* __restrict__ phi,
                          const float* __restrict__ x_enc,
                          const float* __restrict__ m,
                          float* __restrict__ out)
{
    const int wid_g = blockIdx.x * WPB + (threadIdx.x >> 5); // 0..16383
    const int lane  = threadIdx.x & 31;

    const int b   = wid_g >> 11;            // 2048 warps per batch image
    const int hwg = (wid_g & 2047) << 5;    // base hw of this warp's 32 pixels
    const int hw  = hwg + lane;
    const int h   = hw >> 8;
    const int w   = hw & (Wn - 1);

    // ---- per-lane (per-pixel) sampling setup ----
    const float px = phi[(b * 2 + 0) * HWn + hw];
    const float py = phi[(b * 2 + 1) * HWn + hw];
    const float mv = m[b * HWn + hw];

    // vgrid = 2*(coord+phi)/(dim-1) - 1 + 2*phi ; unnormalize (align_corners=False)
    const float vx = 2.0f * ((float)w + px) / (float)(Wn - 1) - 1.0f + 2.0f * px;
    const float vy = 2.0f * ((float)h + py) / (float)(Hn - 1) - 1.0f + 2.0f * py;
    const float ix = (vx + 1.0f) * (0.5f * (float)Wn) - 0.5f;
    const float iy = (vy + 1.0f) * (0.5f * (float)Hn) - 0.5f;

    const float x0f = floorf(ix);
    const float y0f = floorf(iy);
    const int   x0  = (int)x0f;
    const int   y0  = (int)y0f;
    const int   x1  = x0 + 1;
    const int   y1  = y0 + 1;

    const float wx1 = ix - x0f;
    const float wx0 = 1.0f - wx1;
    const float wy1 = iy - y0f;
    const float wy0 = 1.0f - wy1;

    const float vx0 = (x0 >= 0 && x0 < Wn) ? 1.0f : 0.0f;
    const float vx1 = (x1 >= 0 && x1 < Wn) ? 1.0f : 0.0f;
    const float vy0 = (y0 >= 0 && y0 < Hn) ? 1.0f : 0.0f;
    const float vy1 = (y1 >= 0 && y1 < Hn) ? 1.0f : 0.0f;

    // Fold validity AND mask into the corner weights (zeros padding, out *= m)
    const float w00 = wy0 * wx0 * vy0 * vx0 * mv;
    const float w01 = wy0 * wx1 * vy0 * vx1 * mv;
    const float w10 = wy1 * wx0 * vy1 * vx0 * mv;
    const float w11 = wy1 * wx1 * vy1 * vx1 * mv;

    const int x0c = min(max(x0, 0), Wn - 1);
    const int x1c = min(max(x1, 0), Wn - 1);
    const int y0c = min(max(y0, 0), Hn - 1);
    const int y1c = min(max(y1, 0), Hn - 1);

    const int o00 = y0c * Wn + x0c;
    const int o01 = y0c * Wn + x1c;
    const int o10 = y1c * Wn + x0c;
    const int o11 = y1c * Wn + x1c;

    const bool pvalid = (w00 != 0.0f) | (w01 != 0.0f) |
                        (w10 != 0.0f) | (w11 != 0.0f);
    const unsigned blt = __ballot_sync(FULLM, pvalid);

    // Staging: vals[pixel_lane][channel_within_half], padded to 33 to avoid
    // bank conflicts in both access patterns ((i+lane)%32 distinct).
    __shared__ float vals_s[WPB][32 * 33];
    float* __restrict__ V = vals_s[threadIdx.x >> 5];

    const float* __restrict__ pb = x_enc + b * Cn * HWn;
    float* __restrict__ ob = out + b * Cn * HWn + hwg;

#pragma unroll
    for (int half = 0; half < 2; ++half) {
        // ---- cooperative gather: whole warp serves one valid pixel at a
        // time; lane = channel (half*32 + lane). Avg ~1.6 valid/warp. ----
        const float* __restrict__ pc = pb + (half * 32 + lane) * HWn;
        unsigned bb = blt;
        while (bb) {
            const int i = __ffs(bb) - 1;
            bb &= bb - 1;
            const float W00 = __shfl_sync(FULLM, w00, i);
            const float W01 = __shfl_sync(FULLM, w01, i);
            const float W10 = __shfl_sync(FULLM, w10, i);
            const float W11 = __shfl_sync(FULLM, w11, i);
            const int   O00 = __shfl_sync(FULLM, o00, i);
            const int   O01 = __shfl_sync(FULLM, o01, i);
            const int   O10 = __shfl_sync(FULLM, o10, i);
            const int   O11 = __shfl_sync(FULLM, o11, i);
            float v = 0.0f;
            // Uniform branches per broadcast pixel: skip loads for zero corners
            if (W00 != 0.0f) v = fmaf(W00, __ldg(pc + O00), v);
            if (W01 != 0.0f) v = fmaf(W01, __ldg(pc + O01), v);
            if (W10 != 0.0f) v = fmaf(W10, __ldg(pc + O10), v);
            if (W11 != 0.0f) v = fmaf(W11, __ldg(pc + O11), v);
            V[i * 33 + lane] = v;
        }
        __syncwarp();

        // ---- coalesced stores: 32 channel rounds, lane = pixel ----
#pragma unroll 8
        for (int cc = 0; cc < 32; ++cc) {
            const float v = pvalid ? V[lane * 33 + cc] : 0.0f;
            __stcs(ob + (half * 32 + cc) * HWn + lane, v);
        }
        __syncwarp();
    }
}

extern "C" void kernel_launch(void* const* d_in, const int* in_sizes, int n_in,
                              void* d_out, int out_size)
{
    const float* phi   = (const float*)d_in[0];
    const float* x_enc = (const float*)d_in[1];
    const float* m     = (const float*)d_in[2];
    float* out         = (float*)d_out;

    const int nwarps = NPIX / 32;          // 16384 warp-tasks
    const int blocks = nwarps / WPB;       // 4096
    warp_bilinear_kernel<<<blocks, TPB>>>(phi, x_enc, m, out);
}

// round 5
// speedup vs baseline: 1.5488x; 1.5488x over previous
#include <cuda_runtime.h>

// Problem constants (fixed by the reference): B=8, C=64, H=W=256.
#define Bn   8
#define Cn   64
#define Hn   256
#define Wn   256
#define HWn  (Hn * Wn)          // 65536
#define NPIX (Bn * HWn)         // 524288
#define FULLM 0xFFFFFFFFu
#define CPT  8                  // channels per warp-task
#define NCG  (Cn / CPT)         // 8 channel groups
#define WPB  8                  // warps per block
#define TPB  (WPB * 32)

// Layout: warp = 32 consecutive pixels x 8 channels (one cg).
// cg lives in the LOW bits of the warp id, so the 8 warps of a block share
// the same 32 pixels -> phi/m loads hit L1/L2 for 7 of 8 warps.
// Valid-pixel gather work is redistributed across the warp in ONE parallel
// wave (lane = (valid-pixel, channel) task), not a serial per-pixel loop.
__global__ __launch_bounds__(TPB)
void warp_bilinear_kernel(const float* __restrict__ phi,
                          const float* __restrict__ x_enc,
                          const float* __restrict__ m,
                          float* __restrict__ out)
{
    const int wslot = threadIdx.x >> 5;
    const int lane  = threadIdx.x & 31;
    const int wid_g = blockIdx.x * WPB + wslot;

    const int cg      = wid_g & (NCG - 1);
    const int pixwarp = wid_g >> 3;            // 0..16383
    const int b       = pixwarp >> 11;         // 2048 pixel-warps per batch
    const int hwg     = (pixwarp & 2047) << 5; // base hw of the 32 pixels
    const int hw      = hwg + lane;
    const int h       = hw >> 8;
    const int w       = hw & (Wn - 1);

    // ---- per-lane (per-pixel) sampling setup (identical math to R2) ----
    const float px = phi[(b * 2 + 0) * HWn + hw];
    const float py = phi[(b * 2 + 1) * HWn + hw];
    const float mv = m[b * HWn + hw];

    const float vx = 2.0f * ((float)w + px) / (float)(Wn - 1) - 1.0f + 2.0f * px;
    const float vy = 2.0f * ((float)h + py) / (float)(Hn - 1) - 1.0f + 2.0f * py;
    const float ix = (vx + 1.0f) * (0.5f * (float)Wn) - 0.5f;
    const float iy = (vy + 1.0f) * (0.5f * (float)Hn) - 0.5f;

    const float x0f = floorf(ix);
    const float y0f = floorf(iy);
    const int   x0  = (int)x0f;
    const int   y0  = (int)y0f;
    const int   x1  = x0 + 1;
    const int   y1  = y0 + 1;

    const float wx1 = ix - x0f;
    const float wx0 = 1.0f - wx1;
    const float wy1 = iy - y0f;
    const float wy0 = 1.0f - wy1;

    const float vx0 = (x0 >= 0 && x0 < Wn) ? 1.0f : 0.0f;
    const float vx1 = (x1 >= 0 && x1 < Wn) ? 1.0f : 0.0f;
    const float vy0 = (y0 >= 0 && y0 < Hn) ? 1.0f : 0.0f;
    const float vy1 = (y1 >= 0 && y1 < Hn) ? 1.0f : 0.0f;

    // Fold validity AND mask into corner weights (zeros padding, out *= m)
    const float w00 = wy0 * wx0 * vy0 * vx0 * mv;
    const float w01 = wy0 * wx1 * vy0 * vx1 * mv;
    const float w10 = wy1 * wx0 * vy1 * vx0 * mv;
    const float w11 = wy1 * wx1 * vy1 * vx1 * mv;

    const int x0c = min(max(x0, 0), Wn - 1);
    const int x1c = min(max(x1, 0), Wn - 1);
    const int y0c = min(max(y0, 0), Hn - 1);
    const int y1c = min(max(y1, 0), Hn - 1);

    const int o00 = y0c * Wn + x0c;
    const int o01 = y0c * Wn + x1c;
    const int o10 = y1c * Wn + x0c;
    const int o11 = y1c * Wn + x1c;

    const bool pvalid = (w00 != 0.0f) | (w01 != 0.0f) |
                        (w10 != 0.0f) | (w11 != 0.0f);
    const unsigned blt = __ballot_sync(FULLM, pvalid);
    const int rank = __popc(blt & ((1u << lane) - 1u));

    __shared__ int   cmp_s[WPB][32];        // rank -> lane of valid pixel
    __shared__ float res_s[WPB][32 * CPT];  // [rank][channel] gathered values

    if (pvalid) cmp_s[wslot][rank] = lane;
    __syncwarp();

    const int baseC = (b * Cn + cg * CPT) * HWn;

    if (blt) {  // warp-uniform
        const int ntask = __popc(blt) * CPT;  // k valid pixels x 8 channels
        const float* __restrict__ xb = x_enc + baseC;
        for (int base = 0; base < ntask; base += 32) {
            const int  t      = base + lane;
            const bool active = t < ntask;
            const int  j      = t >> 3;      // compacted pixel rank
            const int  ch     = t & 7;
            int src = 0;
            if (active) src = cmp_s[wslot][j];
            // All lanes execute the shuffles (converged); inactive use src=0.
            const float W00 = __shfl_sync(FULLM, w00, src);
            const float W01 = __shfl_sync(FULLM, w01, src);
            const float W10 = __shfl_sync(FULLM, w10, src);
            const float W11 = __shfl_sync(FULLM, w11, src);
            const int   O00 = __shfl_sync(FULLM, o00, src);
            const int   O01 = __shfl_sync(FULLM, o01, src);
            const int   O10 = __shfl_sync(FULLM, o10, src);
            const int   O11 = __shfl_sync(FULLM, o11, src);

            const float* __restrict__ pc = xb + ch * HWn;
            // Batched independent loads (up to 128 in flight warp-wide)
            float a = 0.0f, bv = 0.0f, cv = 0.0f, dv = 0.0f;
            if (active && W00 != 0.0f) a  = __ldg(pc + O00);
            if (active && W01 != 0.0f) bv = __ldg(pc + O01);
            if (active && W10 != 0.0f) cv = __ldg(pc + O10);
            if (active && W11 != 0.0f) dv = __ldg(pc + O11);
            const float acc = fmaf(W00, a, fmaf(W01, bv, fmaf(W10, cv, W11 * dv)));
            if (active) res_s[wslot][j * CPT + ch] = acc;
        }
    }
    __syncwarp();

    // ---- 8 coalesced store rounds; zeros for invalid pixels ----
    float* __restrict__ ob = out + baseC + hwg + lane;
#pragma unroll
    for (int c = 0; c < CPT; ++c) {
        float v = 0.0f;
        if (pvalid) v = res_s[wslot][rank * CPT + c];
        __stcs(ob + c * HWn, v);
    }
}

extern "C" void kernel_launch(void* const* d_in, const int* in_sizes, int n_in,
                              void* d_out, int out_size)
{
    const float* phi   = (const float*)d_in[0];
    const float* x_enc = (const float*)d_in[1];
    const float* m     = (const float*)d_in[2];
    float* out         = (float*)d_out;

    const int nwarps = (NPIX / 32) * NCG;   // 131072 warp-tasks
    const int blocks = nwarps / WPB;        // 16384
    warp_bilinear_kernel<<<blocks, TPB>>>(phi, x_enc, m, out);
}

// round 6
// speedup vs baseline: 1.5563x; 1.0048x over previous
#include <cuda_runtime.h>

// Problem constants (fixed by the reference): B=8, C=64, H=W=256.
#define Bn   8
#define Cn   64
#define Hn   256
#define Wn   256
#define HWn  (Hn * Wn)          // 65536
#define FULLM 0xFFFFFFFFu
#define TPB  256                // 8 warps: block = 32 pixels x 64 channels

__global__ __launch_bounds__(TPB)
void warp_bilinear_kernel(const float* __restrict__ phi,
                          const float* __restrict__ x_enc,
                          const float* __restrict__ m,
                          float* __restrict__ out)
{
    __shared__ float wgt_s[4][32];      // [corner][rank]
    __shared__ int   off_s[4][32];      // [corner][rank]
    __shared__ int   rank_s[32];        // pixel lane -> rank, -1 if invalid
    __shared__ int   nval_s;
    __shared__ float res_s[32 * 65];    // [rank][channel], pad 65 (bank-safe)

    const int tid   = threadIdx.x;
    const int lane  = tid & 31;
    const int wslot = tid >> 5;

    const int pixwarp = blockIdx.x;          // 0..16383: 32-pixel group
    const int b       = pixwarp >> 11;       // 2048 groups per batch image
    const int hwg     = (pixwarp & 2047) << 5;

    // ---- Phase 1: warp 0 computes sampling setup ONCE for the 32 pixels ----
    if (wslot == 0) {
        const int hw = hwg + lane;
        const int h  = hw >> 8;
        const int w  = hw & (Wn - 1);

        const float px = phi[(b * 2 + 0) * HWn + hw];
        const float py = phi[(b * 2 + 1) * HWn + hw];
        const float mv = m[b * HWn + hw];

        // vgrid = 2*(coord+phi)/(dim-1) - 1 + 2*phi ; unnormalize (align_corners=False)
        const float vx = 2.0f * ((float)w + px) / (float)(Wn - 1) - 1.0f + 2.0f * px;
        const float vy = 2.0f * ((float)h + py) / (float)(Hn - 1) - 1.0f + 2.0f * py;
        const float ix = (vx + 1.0f) * (0.5f * (float)Wn) - 0.5f;
        const float iy = (vy + 1.0f) * (0.5f * (float)Hn) - 0.5f;

        const float x0f = floorf(ix);
        const float y0f = floorf(iy);
        const int   x0  = (int)x0f;
        const int   y0  = (int)y0f;
        const int   x1  = x0 + 1;
        const int   y1  = y0 + 1;

        const float wx1 = ix - x0f;
        const float wx0 = 1.0f - wx1;
        const float wy1 = iy - y0f;
        const float wy0 = 1.0f - wy1;

        const float vx0 = (x0 >= 0 && x0 < Wn) ? 1.0f : 0.0f;
        const float vx1 = (x1 >= 0 && x1 < Wn) ? 1.0f : 0.0f;
        const float vy0 = (y0 >= 0 && y0 < Hn) ? 1.0f : 0.0f;
        const float vy1 = (y1 >= 0 && y1 < Hn) ? 1.0f : 0.0f;

        // Fold validity AND mask into corner weights (zeros padding, out *= m)
        const float w00 = wy0 * wx0 * vy0 * vx0 * mv;
        const float w01 = wy0 * wx1 * vy0 * vx1 * mv;
        const float w10 = wy1 * wx0 * vy1 * vx0 * mv;
        const float w11 = wy1 * wx1 * vy1 * vx1 * mv;

        const int x0c = min(max(x0, 0), Wn - 1);
        const int x1c = min(max(x1, 0), Wn - 1);
        const int y0c = min(max(y0, 0), Hn - 1);
        const int y1c = min(max(y1, 0), Hn - 1);

        const bool pvalid = (w00 != 0.0f) | (w01 != 0.0f) |
                            (w10 != 0.0f) | (w11 != 0.0f);
        const unsigned blt = __ballot_sync(FULLM, pvalid);
        const int rank = __popc(blt & ((1u << lane) - 1u));

        rank_s[lane] = pvalid ? rank : -1;
        if (pvalid) {
            wgt_s[0][rank] = w00;  off_s[0][rank] = y0c * Wn + x0c;
            wgt_s[1][rank] = w01;  off_s[1][rank] = y0c * Wn + x1c;
            wgt_s[2][rank] = w10;  off_s[2][rank] = y1c * Wn + x0c;
            wgt_s[3][rank] = w11;  off_s[3][rank] = y1c * Wn + x1c;
        }
        if (lane == 0) nval_s = __popc(blt);
    }
    __syncthreads();

    const int k     = nval_s;
    const int baseB = b * Cn * HWn;

    // ---- Phase 2: block-wide gather, task = (valid pixel rank, channel) ----
    if (k > 0) {
        const int ntask = k << 6;                 // k * 64 channels
        for (int t = tid; t < ntask; t += TPB) {
            const int j  = t >> 6;                // rank
            const int ch = t & 63;
            const float W00 = wgt_s[0][j];
            const float W01 = wgt_s[1][j];
            const float W10 = wgt_s[2][j];
            const float W11 = wgt_s[3][j];
            const int   O00 = off_s[0][j];
            const int   O01 = off_s[1][j];
            const int   O10 = off_s[2][j];
            const int   O11 = off_s[3][j];
            const float* __restrict__ pc = x_enc + baseB + ch * HWn;
            float a = 0.0f, bv = 0.0f, cv = 0.0f, dv = 0.0f;
            if (W00 != 0.0f) a  = __ldg(pc + O00);
            if (W01 != 0.0f) bv = __ldg(pc + O01);
            if (W10 != 0.0f) cv = __ldg(pc + O10);
            if (W11 != 0.0f) dv = __ldg(pc + O11);
            res_s[j * 65 + ch] =
                fmaf(W00, a, fmaf(W01, bv, fmaf(W10, cv, W11 * dv)));
        }
        __syncthreads();
    }

    // ---- Phase 3: coalesced stores; warp wslot owns channels 8*wslot.. ----
    const int r = rank_s[lane];                   // this lane's pixel rank
    const int cbase = wslot << 3;
    float* __restrict__ ob = out + baseB + cbase * HWn + hwg + lane;
#pragma unroll
    for (int c = 0; c < 8; ++c) {
        float v = 0.0f;
        if (r >= 0) v = res_s[r * 65 + cbase + c];
        __stcs(ob + c * HWn, v);
    }
}

extern "C" void kernel_launch(void* const* d_in, const int* in_sizes, int n_in,
                              void* d_out, int out_size)
{
    const float* phi   = (const float*)d_in[0];
    const float* x_enc = (const float*)d_in[1];
    const float* m     = (const float*)d_in[2];
    float* out         = (float*)d_out;

    const int blocks = (Bn * HWn) / 32;    // 16384 pixel-groups
    warp_bilinear_kernel<<<blocks, TPB>>>(phi, x_enc, m, out);
}

// round 7
// speedup vs baseline: 1.5910x; 1.0223x over previous
#include <cuda_runtime.h>

// Problem constants (fixed by the reference): B=8, C=64, H=W=256.
#define Bn   8
#define Cn   64
#define Hn   256
#define Wn   256
#define HWn  (Hn * Wn)          // 65536
#define FULLM 0xFFFFFFFFu
#define TPB  256                // 8 warps: block = 32 pixels x 64 channels

__global__ __launch_bounds__(TPB)
void warp_bilinear_kernel(const float* __restrict__ phi,
                          const float* __restrict__ x_enc,
                          const float* __restrict__ m,
                          float* __restrict__ out)
{
    __shared__ float wgt_s[4][32];      // [corner][rank]
    __shared__ int   off_s[4][32];      // [corner][rank]
    __shared__ int   rank_s[32];        // pixel lane -> rank, -1 if invalid
    __shared__ int   nval_s;
    __shared__ float res_s[32 * 65];    // [rank][channel], pad 65 (bank-safe)

    const int tid   = threadIdx.x;
    const int lane  = tid & 31;
    const int wslot = tid >> 5;

    const int pixwarp = blockIdx.x;          // 0..16383: 32-pixel group
    const int b       = pixwarp >> 11;       // 2048 groups per batch image
    const int hwg     = (pixwarp & 2047) << 5;

    // ---- Phase 1: warp 0 computes sampling setup ONCE for the 32 pixels ----
    if (wslot == 0) {
        const int hw = hwg + lane;
        const int h  = hw >> 8;
        const int w  = hw & (Wn - 1);

        const float px = phi[(b * 2 + 0) * HWn + hw];
        const float py = phi[(b * 2 + 1) * HWn + hw];
        const float mv = m[b * HWn + hw];

        // vgrid = 2*(coord+phi)/(dim-1) - 1 + 2*phi ; unnormalize (align_corners=False)
        const float vx = 2.0f * ((float)w + px) / (float)(Wn - 1) - 1.0f + 2.0f * px;
        const float vy = 2.0f * ((float)h + py) / (float)(Hn - 1) - 1.0f + 2.0f * py;
        const float ix = (vx + 1.0f) * (0.5f * (float)Wn) - 0.5f;
        const float iy = (vy + 1.0f) * (0.5f * (float)Hn) - 0.5f;

        const float x0f = floorf(ix);
        const float y0f = floorf(iy);
        const int   x0  = (int)x0f;
        const int   y0  = (int)y0f;
        const int   x1  = x0 + 1;
        const int   y1  = y0 + 1;

        const float wx1 = ix - x0f;
        const float wx0 = 1.0f - wx1;
        const float wy1 = iy - y0f;
        const float wy0 = 1.0f - wy1;

        const float vx0 = (x0 >= 0 && x0 < Wn) ? 1.0f : 0.0f;
        const float vx1 = (x1 >= 0 && x1 < Wn) ? 1.0f : 0.0f;
        const float vy0 = (y0 >= 0 && y0 < Hn) ? 1.0f : 0.0f;
        const float vy1 = (y1 >= 0 && y1 < Hn) ? 1.0f : 0.0f;

        // Fold validity AND mask into corner weights (zeros padding, out *= m)
        const float w00 = wy0 * wx0 * vy0 * vx0 * mv;
        const float w01 = wy0 * wx1 * vy0 * vx1 * mv;
        const float w10 = wy1 * wx0 * vy1 * vx0 * mv;
        const float w11 = wy1 * wx1 * vy1 * vx1 * mv;

        const int x0c = min(max(x0, 0), Wn - 1);
        const int x1c = min(max(x1, 0), Wn - 1);
        const int y0c = min(max(y0, 0), Hn - 1);
        const int y1c = min(max(y1, 0), Hn - 1);

        const bool pvalid = (w00 != 0.0f) | (w01 != 0.0f) |
                            (w10 != 0.0f) | (w11 != 0.0f);
        const unsigned blt = __ballot_sync(FULLM, pvalid);
        const int rank = __popc(blt & ((1u << lane) - 1u));

        rank_s[lane] = pvalid ? rank : -1;
        if (pvalid) {
            wgt_s[0][rank] = w00;  off_s[0][rank] = y0c * Wn + x0c;
            wgt_s[1][rank] = w01;  off_s[1][rank] = y0c * Wn + x1c;
            wgt_s[2][rank] = w10;  off_s[2][rank] = y1c * Wn + x0c;
            wgt_s[3][rank] = w11;  off_s[3][rank] = y1c * Wn + x1c;
        }
        if (lane == 0) nval_s = __popc(blt);
    }
    __syncthreads();

    const int k     = nval_s;
    const int baseB = b * Cn * HWn;

    // ---- Phase 2: block-wide gather, task = (valid pixel rank, channel) ----
    if (k > 0) {
        const int ntask = k << 6;                 // k * 64 channels
        for (int t = tid; t < ntask; t += TPB) {
            const int j  = t >> 6;                // rank
            const int ch = t & 63;
            const float W00 = wgt_s[0][j];
            const float W01 = wgt_s[1][j];
            const float W10 = wgt_s[2][j];
            const float W11 = wgt_s[3][j];
            const int   O00 = off_s[0][j];
            const int   O01 = off_s[1][j];
            const int   O10 = off_s[2][j];
            const int   O11 = off_s[3][j];
            const float* __restrict__ pc = x_enc + baseB + ch * HWn;
            float a = 0.0f, bv = 0.0f, cv = 0.0f, dv = 0.0f;
            if (W00 != 0.0f) a  = __ldg(pc + O00);
            if (W01 != 0.0f) bv = __ldg(pc + O01);
            if (W10 != 0.0f) cv = __ldg(pc + O10);
            if (W11 != 0.0f) dv = __ldg(pc + O11);
            res_s[j * 65 + ch] =
                fmaf(W00, a, fmaf(W01, bv, fmaf(W10, cv, W11 * dv)));
        }
        __syncthreads();
    }

    // ---- Phase 3: vectorized stores. Thread t owns (channel = t>>3,
    // pixel quad = 4*(t&7)); 2 rounds of STG.128 cover 64ch x 32px. ----
    const int q  = (tid & 7) << 2;                // pixel base within group
    const int r0 = rank_s[q + 0];
    const int r1 = rank_s[q + 1];
    const int r2 = rank_s[q + 2];
    const int r3 = rank_s[q + 3];

#pragma unroll
    for (int rd = 0; rd < 2; ++rd) {
        const int ch = (tid >> 3) + (rd << 5);    // 0..63
        float4 v;
        v.x = (r0 >= 0) ? res_s[r0 * 65 + ch] : 0.0f;
        v.y = (r1 >= 0) ? res_s[r1 * 65 + ch] : 0.0f;
        v.z = (r2 >= 0) ? res_s[r2 * 65 + ch] : 0.0f;
        v.w = (r3 >= 0) ? res_s[r3 * 65 + ch] : 0.0f;
        __stcs((float4*)(out + baseB + ch * HWn + hwg + q), v);
    }
}

extern "C" void kernel_launch(void* const* d_in, const int* in_sizes, int n_in,
                              void* d_out, int out_size)
{
    const float* phi   = (const float*)d_in[0];
    const float* x_enc = (const float*)d_in[1];
    const float* m     = (const float*)d_in[2];
    float* out         = (float*)d_out;

    const int blocks = (Bn * HWn) / 32;    // 16384 pixel-groups
    warp_bilinear_kernel<<<blocks, TPB>>>(phi, x_enc, m, out);
}